// round 16
// baseline (speedup 1.0000x reference)
#include <cuda_runtime.h>
#include <cuda_fp16.h>
#include <math.h>
#include <stdint.h>

#define T_TOK 8192
#define DIMSZ 512
#define HIDSZ 1024
#define NE    8

// ---------------- device scratch ----------------
__device__ int    g_count[NE];
__device__ int    g_list[NE][T_TOK];
__device__ float  g_p[T_TOK * 2];
__device__ __half g_h[(size_t)T_TOK * 2 * HIDSZ];
__device__ __half g_hs[(size_t)T_TOK * HIDSZ];

__device__ __half g_xh[(size_t)T_TOK * DIMSZ];
__device__ __half g_w1h[(size_t)NE * DIMSZ * HIDSZ];   // natural [E][D][H]
__device__ __half g_w3h[(size_t)NE * DIMSZ * HIDSZ];
__device__ __half g_w2h[(size_t)NE * HIDSZ * DIMSZ];   // natural [E][H][D]
__device__ __half g_sw1h[(size_t)DIMSZ * HIDSZ];
__device__ __half g_sw3h[(size_t)DIMSZ * HIDSZ];
__device__ __half g_sw2h[(size_t)HIDSZ * DIMSZ];

// ---------------- helpers ----------------
__device__ __forceinline__ uint32_t smem_u32(const void* p) {
    uint32_t a;
    asm("{ .reg .u64 t; cvta.to.shared.u64 t, %1; cvt.u32.u64 %0, t; }" : "=r"(a) : "l"(p));
    return a;
}
__device__ __forceinline__ void cp16(uint32_t saddr, const void* g) {
    asm volatile("cp.async.cg.shared.global [%0], [%1], 16;" :: "r"(saddr), "l"(g));
}
#define CP_COMMIT()  asm volatile("cp.async.commit_group;")
#define CP_WAIT(N)   asm volatile("cp.async.wait_group %0;" :: "n"(N))

#define LDSM4(R, addr)                                                          \
    asm volatile("ldmatrix.sync.aligned.m8n8.x4.shared.b16 {%0,%1,%2,%3}, [%4];"\
        : "=r"((R)[0]), "=r"((R)[1]), "=r"((R)[2]), "=r"((R)[3]) : "r"(addr))

#define LDSM4T(R, addr)                                                         \
    asm volatile("ldmatrix.sync.aligned.m8n8.x4.trans.shared.b16 {%0,%1,%2,%3}, [%4];"\
        : "=r"((R)[0]), "=r"((R)[1]), "=r"((R)[2]), "=r"((R)[3]) : "r"(addr))

#define MMA16816(C, A, B0, B1)                                                  \
    asm volatile(                                                               \
        "mma.sync.aligned.m16n8k16.row.col.f32.f16.f16.f32 "                    \
        "{%0,%1,%2,%3}, {%4,%5,%6,%7}, {%8,%9}, {%0,%1,%2,%3};"                 \
        : "+f"((C)[0]), "+f"((C)[1]), "+f"((C)[2]), "+f"((C)[3])                 \
        : "r"((A)[0]), "r"((A)[1]), "r"((A)[2]), "r"((A)[3]), "r"(B0), "r"(B1))

__device__ __forceinline__ uint32_t swz(uint32_t off) {   // SW128 (Swizzle<3,4,3>)
    return off ^ ((off >> 3) & 0x70);
}
__device__ __forceinline__ float fast_silu_mul(float u, float v) {
    return (u / (1.f + __expf(-u))) * v;
}

// ---------------- small kernels ----------------
__global__ void reset_counts_kernel() {
    if (threadIdx.x < NE) g_count[threadIdx.x] = 0;
}

// Segmented conversion for the 6 weight tensors (x handled by router). MLP=2.
#define SEG_W   1048576
#define SEG_S   131072
#define CVT_TOT (3 * SEG_W + 3 * SEG_S)
#define CVT_HALF (CVT_TOT / 2)
__device__ __forceinline__ void cvt_one(int i,
                                        const float* w1, const float* w3, const float* w2,
                                        const float* sw1, const float* sw3, const float* sw2) {
    const float* src;
    __half* dst;
    int off;
    if (i < SEG_W)                      { src = w1; dst = g_w1h; off = i; }
    else if (i < 2 * SEG_W)             { src = w3; dst = g_w3h; off = i - SEG_W; }
    else if (i < 3 * SEG_W)             { src = w2; dst = g_w2h; off = i - 2 * SEG_W; }
    else if (i < 3 * SEG_W + SEG_S)     { src = sw1; dst = g_sw1h; off = i - 3 * SEG_W; }
    else if (i < 3 * SEG_W + 2 * SEG_S) { src = sw3; dst = g_sw3h; off = i - 3 * SEG_W - SEG_S; }
    else                                { src = sw2; dst = g_sw2h; off = i - 3 * SEG_W - 2 * SEG_S; }
    float4 v = ((const float4*)src)[off];
    __half2* o = reinterpret_cast<__half2*>(dst) + 2 * off;
    o[0] = __floats2half2_rn(v.x, v.y);
    o[1] = __floats2half2_rn(v.z, v.w);
}
__global__ void cvt_all_kernel(const float* __restrict__ w1,
                               const float* __restrict__ w3,
                               const float* __restrict__ w2,
                               const float* __restrict__ sw1,
                               const float* __restrict__ sw3,
                               const float* __restrict__ sw2) {
    int i = blockIdx.x * blockDim.x + threadIdx.x;
    if (i >= CVT_HALF) return;
    cvt_one(i, w1, w3, w2, sw1, sw3, sw2);
    cvt_one(i + CVT_HALF, w1, w3, w2, sw1, sw3, sw2);
}

// router: scores (float4) + top2 + gates + lists; converts x -> g_xh; zeroes out.
__global__ void router_kernel(const float* __restrict__ x,
                              const float* __restrict__ gw,
                              const float* __restrict__ biases,
                              float* __restrict__ out) {
    {
        int gt = blockIdx.x * blockDim.x + threadIdx.x;
        float4 z = make_float4(0.f, 0.f, 0.f, 0.f);
#pragma unroll
        for (int k = 0; k < 4; k++)
            ((float4*)out)[gt + k * 262144] = z;
    }

    int warp = (blockIdx.x * blockDim.x + threadIdx.x) >> 5;
    int lane = threadIdx.x & 31;
    const float* xt = x + (size_t)warp * DIMSZ;
    __half2* xo = (__half2*)(g_xh + (size_t)warp * DIMSZ);

    float sc[NE];
#pragma unroll
    for (int e = 0; e < NE; e++) sc[e] = 0.f;
#pragma unroll
    for (int it = 0; it < 4; it++) {
        int i4 = lane + it * 32;
        float4 xv = ((const float4*)xt)[i4];
        xo[i4 * 2 + 0] = __floats2half2_rn(xv.x, xv.y);
        xo[i4 * 2 + 1] = __floats2half2_rn(xv.z, xv.w);
#pragma unroll
        for (int e = 0; e < NE; e++) {
            float4 gv = ((const float4*)(gw + e * DIMSZ))[i4];
            sc[e] += xv.x * gv.x + xv.y * gv.y + xv.z * gv.z + xv.w * gv.w;
        }
    }
#pragma unroll
    for (int e = 0; e < NE; e++) {
#pragma unroll
        for (int off = 16; off; off >>= 1)
            sc[e] += __shfl_xor_sync(0xffffffffu, sc[e], off);
    }
    if (lane != 0) return;

    float b[NE];
#pragma unroll
    for (int e = 0; e < NE; e++) b[e] = sc[e] + biases[e];
    int i0 = 0;
#pragma unroll
    for (int e = 1; e < NE; e++) if (b[e] > b[i0]) i0 = e;
    int i1 = (i0 == 0) ? 1 : 0;
#pragma unroll
    for (int e = 0; e < NE; e++) if (e != i0 && b[e] > b[i1]) i1 = e;

    int a0 = 0;
#pragma unroll
    for (int e = 1; e < NE; e++) if (sc[e] > sc[a0]) a0 = e;
    int a1 = (a0 == 0) ? 1 : 0;
#pragma unroll
    for (int e = 0; e < NE; e++) if (e != a0 && sc[e] > sc[a1]) a1 = e;

    float p0 = 1.f / (1.f + expf(-sc[a0]));
    float p1 = 1.f / (1.f + expf(-sc[a1]));
    float s = p0 + p1;
    p0 /= s; p1 /= s;

    int t = warp;
    int pos0 = atomicAdd(&g_count[i0], 1);
    g_list[i0][pos0] = t * 2 + 0;
    g_p[t * 2 + 0] = p0;
    int pos1 = atomicAdd(&g_count[i1], 1);
    g_list[i1][pos1] = t * 2 + 1;
    g_p[t * 2 + 1] = p1;
}

// ================= up projection =================
// CTA 256(M) x 64(N), BK=64, dual B. 8 warps (4m x 2n), warp tile 64x32-per-matrix.
// 128 B smem traffic per MMA (1:1 with tensor). 4-stage ring, 48KB/stage, 1 CTA/SM.
#define UP_STG 49152    // A 32KB + B1 8KB + B3 8KB
__global__ __launch_bounds__(256, 1) void moe_up_h(const __half* __restrict__ w1h,
                                                   const __half* __restrict__ w3h,
                                                   const __half* __restrict__ sw1h,
                                                   const __half* __restrict__ sw3h) {
    extern __shared__ char dsm[];
    __shared__ int sSlot[256];
    __shared__ int sTok[256];

    int e = blockIdx.z;
    bool shared_e = (e == NE);
    int M = shared_e ? T_TOK : g_count[e];
    int row0 = blockIdx.x * 256;
    if (row0 >= M) return;
    int col0 = blockIdx.y * 64;
    const __half* W1 = shared_e ? sw1h : (w1h + (size_t)e * DIMSZ * HIDSZ);   // [D][H]
    const __half* W3 = shared_e ? sw3h : (w3h + (size_t)e * DIMSZ * HIDSZ);
    __half* hout = shared_e ? g_hs : g_h;

    uint32_t base = smem_u32(dsm);

    int tid = threadIdx.x, lane = tid & 31, warp = tid >> 5;
    {
        int r = row0 + tid;
        int sl = (r < M) ? (shared_e ? r : g_list[e][r]) : -1;
        sSlot[tid] = sl;
        sTok[tid] = (sl < 0) ? 0 : (shared_e ? sl : (sl >> 1));
    }
    __syncthreads();

    int wm = warp >> 1, wc = warp & 1;
    int wr0 = wm * 64, wn0 = wc * 32;

    int ar = tid >> 3, ac = tid & 7;     // A: 32 base rows x 8 chunks; 8/thread
    int bk = tid >> 3, bc = tid & 7;     // B: 2/thread per matrix

    const __half* aPtr[8];
#pragma unroll
    for (int j = 0; j < 8; j++)
        aPtr[j] = g_xh + (size_t)sTok[ar + j * 32] * DIMSZ + ac * 8;

    auto loadStage = [&](int st, int ch) {
        uint32_t sb = base + st * UP_STG;
#pragma unroll
        for (int j = 0; j < 8; j++) {
            int row = ar + j * 32;
            uint32_t sw = swz(row * 128 + ac * 16);
            cp16(sb + sw, aPtr[j] + ch * 64);
        }
#pragma unroll
        for (int j = 0; j < 2; j++) {
            int kr = bk + j * 32;
            uint32_t sw = swz(kr * 128 + bc * 16);
            cp16(sb + 32768 + sw, W1 + (size_t)(ch * 64 + kr) * HIDSZ + col0 + bc * 8);
            cp16(sb + 40960 + sw, W3 + (size_t)(ch * 64 + kr) * HIDSZ + col0 + bc * 8);
        }
    };

    float acc1[4][4][4] = {};
    float acc3[4][4][4] = {};

    const int nCh = DIMSZ / 64;   // 8
    loadStage(0, 0); CP_COMMIT();
    loadStage(1, 1); CP_COMMIT();
    loadStage(2, 2); CP_COMMIT();

    int aRowF = (lane & 15);
    int aColF = (lane >> 4) << 3;
    int bKF = (lane & 7) + ((lane >> 3) & 1) * 8;
    int bNF = ((lane >> 4) & 1) * 8;

    for (int c = 0; c < nCh; c++) {
        CP_WAIT(2);
        __syncthreads();
        if (c + 3 < nCh) loadStage((c + 3) & 3, c + 3);
        CP_COMMIT();                                   // may be empty group

        uint32_t sA = base + (c & 3) * UP_STG;
        uint32_t sB1 = sA + 32768;
        uint32_t sB3 = sA + 40960;
#pragma unroll
        for (int kk = 0; kk < 4; kk++) {
            uint32_t a[4][4], b1[2][4], b3[2][4];
#pragma unroll
            for (int ma = 0; ma < 4; ma++) {
                int row = wr0 + ma * 16 + aRowF;
                uint32_t off = swz(row * 128 + (kk * 16 + aColF) * 2);
                LDSM4(a[ma], sA + off);
            }
#pragma unroll
            for (int nb = 0; nb < 2; nb++) {
                uint32_t off = swz((kk * 16 + bKF) * 128 + (wn0 + nb * 16 + bNF) * 2);
                LDSM4T(b1[nb], sB1 + off);
                LDSM4T(b3[nb], sB3 + off);
            }
#pragma unroll
            for (int ma = 0; ma < 4; ma++) {
#pragma unroll
                for (int nb = 0; nb < 2; nb++) {
#pragma unroll
                    for (int h = 0; h < 2; h++) {
                        MMA16816(acc1[ma][nb * 2 + h], a[ma], b1[nb][2 * h], b1[nb][2 * h + 1]);
                        MMA16816(acc3[ma][nb * 2 + h], a[ma], b3[nb][2 * h], b3[nb][2 * h + 1]);
                    }
                }
            }
        }
    }

    // epilogue: silu(acc1)*acc3 -> fp16 store
    int cRow = lane >> 2, cCol = (lane & 3) * 2;
#pragma unroll
    for (int ma = 0; ma < 4; ma++) {
#pragma unroll
        for (int half = 0; half < 2; half++) {
            int rl = wr0 + ma * 16 + half * 8 + cRow;
            int slot = sSlot[rl];
            if (slot < 0) continue;
            __half* hp = hout + (size_t)slot * HIDSZ + col0 + wn0;
#pragma unroll
            for (int na = 0; na < 4; na++) {
                float o0 = fast_silu_mul(acc1[ma][na][half * 2 + 0], acc3[ma][na][half * 2 + 0]);
                float o1 = fast_silu_mul(acc1[ma][na][half * 2 + 1], acc3[ma][na][half * 2 + 1]);
                *(__half2*)(hp + na * 8 + cCol) = __floats2half2_rn(o0, o1);
            }
        }
    }
}

// ================= down projection =================
// CTA 256(M) x 128(N), BK=64. 8 warps (4m x 2n), warp tile 64x64 (n-half = B panel).
// 128 B smem traffic per MMA. 4-stage ring, 48KB/stage, 1 CTA/SM. RED-add into out.
#define DN_STG 49152    // A 32KB + B 16KB (two 8KB panels)
__global__ __launch_bounds__(256, 1) void moe_down_h(const __half* __restrict__ w2h,
                                                     const __half* __restrict__ sw2h,
                                                     float* __restrict__ out) {
    extern __shared__ char dsm[];
    __shared__ int sSlot[256];

    int e = blockIdx.z;
    bool shared_e = (e == NE);
    int M = shared_e ? T_TOK : g_count[e];
    int row0 = blockIdx.x * 256;
    if (row0 >= M) return;
    int col0 = blockIdx.y * 128;
    const __half* W2 = shared_e ? sw2h : (w2h + (size_t)e * HIDSZ * DIMSZ);   // [H][D]
    const __half* hin = shared_e ? g_hs : g_h;

    uint32_t base = smem_u32(dsm);

    int tid = threadIdx.x, lane = tid & 31, warp = tid >> 5;
    {
        int r = row0 + tid;
        sSlot[tid] = (r < M) ? (shared_e ? r : g_list[e][r]) : -1;
    }
    __syncthreads();

    int wm = warp >> 1, wc = warp & 1;
    int wr0 = wm * 64;                 // warp covers 64 rows
    // warp covers cols [wc*64, wc*64+64) = panel wc

    int ar = tid >> 3, ac = tid & 7;

    const __half* aPtr[8];
#pragma unroll
    for (int j = 0; j < 8; j++) {
        int sl = sSlot[ar + j * 32];
        aPtr[j] = hin + (size_t)((sl < 0) ? 0 : sl) * HIDSZ + ac * 8;
    }

    auto loadStage = [&](int st, int ch) {
        uint32_t sb = base + st * DN_STG;
#pragma unroll
        for (int j = 0; j < 8; j++) {
            int row = ar + j * 32;
            uint32_t sw = swz(row * 128 + ac * 16);
            cp16(sb + sw, aPtr[j] + ch * 64);
        }
        // B: 64 k-rows x 2 panels x 8 chunks = 1024 chunks, 4/thread
#pragma unroll
        for (int j = 0; j < 4; j++) {
            int idx = tid + j * 256;
            int pnl = idx >> 9;
            int rem = idx & 511;
            int kr = rem >> 3;
            int nc = rem & 7;
            uint32_t sw = swz(kr * 128 + nc * 16);
            cp16(sb + 32768 + pnl * 8192 + sw,
                 W2 + (size_t)(ch * 64 + kr) * DIMSZ + col0 + pnl * 64 + nc * 8);
        }
    };

    float acc[4][8][4] = {};

    const int nCh = HIDSZ / 64;   // 16
    loadStage(0, 0); CP_COMMIT();
    loadStage(1, 1); CP_COMMIT();
    loadStage(2, 2); CP_COMMIT();

    int aRowF = (lane & 15);
    int aColF = (lane >> 4) << 3;
    int bKF = (lane & 7) + ((lane >> 3) & 1) * 8;
    int bNF = ((lane >> 4) & 1) * 8;

    for (int c = 0; c < nCh; c++) {
        CP_WAIT(2);
        __syncthreads();
        if (c + 3 < nCh) loadStage((c + 3) & 3, c + 3);
        CP_COMMIT();

        uint32_t sA = base + (c & 3) * DN_STG;
        uint32_t sB = sA + 32768 + wc * 8192;
#pragma unroll
        for (int kk = 0; kk < 4; kk++) {
            uint32_t a[4][4], b[4][4];
#pragma unroll
            for (int ma = 0; ma < 4; ma++) {
                int row = wr0 + ma * 16 + aRowF;
                uint32_t off = swz(row * 128 + (kk * 16 + aColF) * 2);
                LDSM4(a[ma], sA + off);
            }
#pragma unroll
            for (int nb = 0; nb < 4; nb++) {
                uint32_t off = swz((kk * 16 + bKF) * 128 + (nb * 16 + bNF) * 2);
                LDSM4T(b[nb], sB + off);
            }
#pragma unroll
            for (int ma = 0; ma < 4; ma++) {
#pragma unroll
                for (int nb = 0; nb < 4; nb++) {
#pragma unroll
                    for (int h = 0; h < 2; h++) {
                        MMA16816(acc[ma][nb * 2 + h], a[ma], b[nb][2 * h], b[nb][2 * h + 1]);
                    }
                }
            }
        }
    }

    // epilogue: RED-add scaled results into out[token]
    int cRow = lane >> 2, cCol = (lane & 3) * 2;
#pragma unroll
    for (int ma = 0; ma < 4; ma++) {
#pragma unroll
        for (int half = 0; half < 2; half++) {
            int rl = wr0 + ma * 16 + half * 8 + cRow;
            int slot = sSlot[rl];
            if (slot < 0) continue;
            int token = shared_e ? slot : (slot >> 1);
            float scale = shared_e ? 1.f : g_p[slot];
            float* yp = out + (size_t)token * DIMSZ + col0 + wc * 64;
#pragma unroll
            for (int na = 0; na < 8; na++) {
                atomicAdd(yp + na * 8 + cCol + 0, scale * acc[ma][na][half * 2 + 0]);
                atomicAdd(yp + na * 8 + cCol + 1, scale * acc[ma][na][half * 2 + 1]);
            }
        }
    }
}

// ---------------- launcher ----------------
extern "C" void kernel_launch(void* const* d_in, const int* in_sizes, int n_in,
                              void* d_out, int out_size) {
    const float* x      = (const float*)d_in[0];
    const float* gate_w = (const float*)d_in[1];
    const float* biases = (const float*)d_in[2];
    const float* w1     = (const float*)d_in[3];
    const float* w3     = (const float*)d_in[4];
    const float* w2     = (const float*)d_in[5];
    const float* sw1    = (const float*)d_in[6];
    const float* sw3    = (const float*)d_in[7];
    const float* sw2    = (const float*)d_in[8];
    float* out          = (float*)d_out;

    const int upSmem = 4 * UP_STG;   // 196608
    const int dnSmem = 4 * DN_STG;   // 196608
    cudaFuncSetAttribute(moe_up_h,   cudaFuncAttributeMaxDynamicSharedMemorySize, upSmem);
    cudaFuncSetAttribute(moe_down_h, cudaFuncAttributeMaxDynamicSharedMemorySize, dnSmem);

    __half *w1h, *w3h, *w2h, *sw1h, *sw3h, *sw2h;
    cudaGetSymbolAddress((void**)&w1h,  g_w1h);
    cudaGetSymbolAddress((void**)&w3h,  g_w3h);
    cudaGetSymbolAddress((void**)&w2h,  g_w2h);
    cudaGetSymbolAddress((void**)&sw1h, g_sw1h);
    cudaGetSymbolAddress((void**)&sw3h, g_sw3h);
    cudaGetSymbolAddress((void**)&sw2h, g_sw2h);

    reset_counts_kernel<<<1, 32>>>();
    router_kernel<<<T_TOK / 8, 256>>>(x, gate_w, biases, out);
    cvt_all_kernel<<<(CVT_HALF + 255) / 256, 256>>>(w1, w3, w2, sw1, sw3, sw2);

    // fused: routed experts (z=0..7) + shared expert (z=8)
    moe_up_h<<<dim3(T_TOK / 256, HIDSZ / 64, NE + 1), 256, upSmem>>>(w1h, w3h, sw1h, sw3h);
    moe_down_h<<<dim3(T_TOK / 256, DIMSZ / 128, NE + 1), 256, dnSmem>>>(w2h, sw2h, out);
}

// round 17
// speedup vs baseline: 1.7320x; 1.7320x over previous
#include <cuda_runtime.h>
#include <cuda_fp16.h>
#include <math.h>
#include <stdint.h>

#define T_TOK 8192
#define DIMSZ 512
#define HIDSZ 1024
#define NE    8

// ---------------- device scratch ----------------
__device__ int    g_count[NE];
__device__ int    g_list[NE][T_TOK];
__device__ float  g_p[T_TOK * 2];
__device__ __half g_h[(size_t)T_TOK * 2 * HIDSZ];
__device__ __half g_hs[(size_t)T_TOK * HIDSZ];

__device__ __half g_xh[(size_t)T_TOK * DIMSZ];
__device__ __half g_w1h[(size_t)NE * DIMSZ * HIDSZ];   // natural [E][D][H]
__device__ __half g_w3h[(size_t)NE * DIMSZ * HIDSZ];
__device__ __half g_w2h[(size_t)NE * HIDSZ * DIMSZ];   // natural [E][H][D]
__device__ __half g_sw1h[(size_t)DIMSZ * HIDSZ];
__device__ __half g_sw3h[(size_t)DIMSZ * HIDSZ];
__device__ __half g_sw2h[(size_t)HIDSZ * DIMSZ];

// ---------------- helpers ----------------
__device__ __forceinline__ uint32_t smem_u32(const void* p) {
    uint32_t a;
    asm("{ .reg .u64 t; cvta.to.shared.u64 t, %1; cvt.u32.u64 %0, t; }" : "=r"(a) : "l"(p));
    return a;
}
__device__ __forceinline__ void cp16(uint32_t saddr, const void* g) {
    asm volatile("cp.async.cg.shared.global [%0], [%1], 16;" :: "r"(saddr), "l"(g));
}
#define CP_COMMIT()  asm volatile("cp.async.commit_group;")
#define CP_WAIT(N)   asm volatile("cp.async.wait_group %0;" :: "n"(N))

#define LDSM4(R, addr)                                                          \
    asm volatile("ldmatrix.sync.aligned.m8n8.x4.shared.b16 {%0,%1,%2,%3}, [%4];"\
        : "=r"((R)[0]), "=r"((R)[1]), "=r"((R)[2]), "=r"((R)[3]) : "r"(addr))

#define LDSM4T(R, addr)                                                         \
    asm volatile("ldmatrix.sync.aligned.m8n8.x4.trans.shared.b16 {%0,%1,%2,%3}, [%4];"\
        : "=r"((R)[0]), "=r"((R)[1]), "=r"((R)[2]), "=r"((R)[3]) : "r"(addr))

#define MMA16816(C, A, B0, B1)                                                  \
    asm volatile(                                                               \
        "mma.sync.aligned.m16n8k16.row.col.f32.f16.f16.f32 "                    \
        "{%0,%1,%2,%3}, {%4,%5,%6,%7}, {%8,%9}, {%0,%1,%2,%3};"                 \
        : "+f"((C)[0]), "+f"((C)[1]), "+f"((C)[2]), "+f"((C)[3])                 \
        : "r"((A)[0]), "r"((A)[1]), "r"((A)[2]), "r"((A)[3]), "r"(B0), "r"(B1))

__device__ __forceinline__ uint32_t swz(uint32_t off) {   // SW128 (Swizzle<3,4,3>)
    return off ^ ((off >> 3) & 0x70);
}
__device__ __forceinline__ float fast_silu_mul(float u, float v) {
    return (u / (1.f + __expf(-u))) * v;
}

// ---------------- small kernels ----------------
__global__ void reset_counts_kernel() {
    if (threadIdx.x < NE) g_count[threadIdx.x] = 0;
}

// Segmented conversion for the 6 weight tensors (x handled by router). MLP=2.
#define SEG_W   1048576                      // 8*512*1024/4
#define SEG_S   131072                       // 512*1024/4
#define CVT_TOT (3 * SEG_W + 3 * SEG_S)
#define CVT_HALF (CVT_TOT / 2)
__device__ __forceinline__ void cvt_one(int i,
                                        const float* w1, const float* w3, const float* w2,
                                        const float* sw1, const float* sw3, const float* sw2) {
    const float* src;
    __half* dst;
    int off;
    if (i < SEG_W)                      { src = w1; dst = g_w1h; off = i; }
    else if (i < 2 * SEG_W)             { src = w3; dst = g_w3h; off = i - SEG_W; }
    else if (i < 3 * SEG_W)             { src = w2; dst = g_w2h; off = i - 2 * SEG_W; }
    else if (i < 3 * SEG_W + SEG_S)     { src = sw1; dst = g_sw1h; off = i - 3 * SEG_W; }
    else if (i < 3 * SEG_W + 2 * SEG_S) { src = sw3; dst = g_sw3h; off = i - 3 * SEG_W - SEG_S; }
    else                                { src = sw2; dst = g_sw2h; off = i - 3 * SEG_W - 2 * SEG_S; }
    float4 v = ((const float4*)src)[off];
    __half2* o = reinterpret_cast<__half2*>(dst) + 2 * off;
    o[0] = __floats2half2_rn(v.x, v.y);
    o[1] = __floats2half2_rn(v.z, v.w);
}
__global__ void cvt_all_kernel(const float* __restrict__ w1,
                               const float* __restrict__ w3,
                               const float* __restrict__ w2,
                               const float* __restrict__ sw1,
                               const float* __restrict__ sw3,
                               const float* __restrict__ sw2) {
    int i = blockIdx.x * blockDim.x + threadIdx.x;
    if (i >= CVT_HALF) return;
    cvt_one(i, w1, w3, w2, sw1, sw3, sw2);
    cvt_one(i + CVT_HALF, w1, w3, w2, sw1, sw3, sw2);
}

// router: scores (float4) + top2 + gates + lists; converts x -> g_xh; zeroes out.
__global__ void router_kernel(const float* __restrict__ x,
                              const float* __restrict__ gw,
                              const float* __restrict__ biases,
                              float* __restrict__ out) {
    // fused out-zeroing: 262144 threads x 4 float4 = T*D floats
    {
        int gt = blockIdx.x * blockDim.x + threadIdx.x;
        float4 z = make_float4(0.f, 0.f, 0.f, 0.f);
#pragma unroll
        for (int k = 0; k < 4; k++)
            ((float4*)out)[gt + k * 262144] = z;
    }

    int warp = (blockIdx.x * blockDim.x + threadIdx.x) >> 5;
    int lane = threadIdx.x & 31;
    const float* xt = x + (size_t)warp * DIMSZ;
    __half2* xo = (__half2*)(g_xh + (size_t)warp * DIMSZ);

    float sc[NE];
#pragma unroll
    for (int e = 0; e < NE; e++) sc[e] = 0.f;
#pragma unroll
    for (int it = 0; it < 4; it++) {
        int i4 = lane + it * 32;                       // float4 index, 0..127
        float4 xv = ((const float4*)xt)[i4];
        xo[i4 * 2 + 0] = __floats2half2_rn(xv.x, xv.y);
        xo[i4 * 2 + 1] = __floats2half2_rn(xv.z, xv.w);
#pragma unroll
        for (int e = 0; e < NE; e++) {
            float4 gv = ((const float4*)(gw + e * DIMSZ))[i4];
            sc[e] += xv.x * gv.x + xv.y * gv.y + xv.z * gv.z + xv.w * gv.w;
        }
    }
#pragma unroll
    for (int e = 0; e < NE; e++) {
#pragma unroll
        for (int off = 16; off; off >>= 1)
            sc[e] += __shfl_xor_sync(0xffffffffu, sc[e], off);
    }
    if (lane != 0) return;

    float b[NE];
#pragma unroll
    for (int e = 0; e < NE; e++) b[e] = sc[e] + biases[e];
    int i0 = 0;
#pragma unroll
    for (int e = 1; e < NE; e++) if (b[e] > b[i0]) i0 = e;
    int i1 = (i0 == 0) ? 1 : 0;
#pragma unroll
    for (int e = 0; e < NE; e++) if (e != i0 && b[e] > b[i1]) i1 = e;

    int a0 = 0;
#pragma unroll
    for (int e = 1; e < NE; e++) if (sc[e] > sc[a0]) a0 = e;
    int a1 = (a0 == 0) ? 1 : 0;
#pragma unroll
    for (int e = 0; e < NE; e++) if (e != a0 && sc[e] > sc[a1]) a1 = e;

    float p0 = 1.f / (1.f + expf(-sc[a0]));
    float p1 = 1.f / (1.f + expf(-sc[a1]));
    float s = p0 + p1;
    p0 /= s; p1 /= s;

    int t = warp;
    int pos0 = atomicAdd(&g_count[i0], 1);
    g_list[i0][pos0] = t * 2 + 0;
    g_p[t * 2 + 0] = p0;
    int pos1 = atomicAdd(&g_count[i1], 1);
    g_list[i1][pos1] = t * 2 + 1;
    g_p[t * 2 + 1] = p1;
}

// ================= up projection =================
// CTA 128(M) x 64(N), BK=64. 8 warps (4m x 2n), warp tile 32x32, dual B (w1,w3).
// Single __syncthreads per chunk (wait -> sync -> issue-next -> compute).
#define UP_STG 32768
__global__ __launch_bounds__(256, 2) void moe_up_h(const __half* __restrict__ w1h,
                                                   const __half* __restrict__ w3h,
                                                   const __half* __restrict__ sw1h,
                                                   const __half* __restrict__ sw3h) {
    extern __shared__ char dsm[];
    __shared__ int sSlot[128];
    __shared__ int sTok[128];

    int e = blockIdx.z;
    bool shared_e = (e == NE);
    int M = shared_e ? T_TOK : g_count[e];
    int row0 = blockIdx.x * 128;
    if (row0 >= M) return;
    int col0 = blockIdx.y * 64;
    const __half* W1 = shared_e ? sw1h : (w1h + (size_t)e * DIMSZ * HIDSZ);   // [D][H]
    const __half* W3 = shared_e ? sw3h : (w3h + (size_t)e * DIMSZ * HIDSZ);
    __half* hout = shared_e ? g_hs : g_h;

    uint32_t base = smem_u32(dsm);

    int tid = threadIdx.x, lane = tid & 31, warp = tid >> 5;
    if (tid < 128) {
        int r = row0 + tid;
        int sl = (r < M) ? (shared_e ? r : g_list[e][r]) : -1;
        sSlot[tid] = sl;
        sTok[tid] = (sl < 0) ? 0 : (shared_e ? sl : (sl >> 1));
    }
    __syncthreads();

    int wm = warp >> 1, wc = warp & 1;
    int wr0 = wm * 32, wn0 = wc * 32;

    int ar = tid >> 3, ac = tid & 7;
    int bk = tid >> 3, bc = tid & 7;

    // hoisted A-row base pointers (4 per thread, fixed across stages)
    const __half* aPtr[4];
#pragma unroll
    for (int j = 0; j < 4; j++)
        aPtr[j] = g_xh + (size_t)sTok[ar + j * 32] * DIMSZ + ac * 8;

    auto loadStage = [&](int st, int ch) {
        uint32_t sb = base + st * UP_STG;
#pragma unroll
        for (int j = 0; j < 4; j++) {
            int row = ar + j * 32;
            uint32_t sw = swz(row * 128 + ac * 16);
            cp16(sb + sw, aPtr[j] + ch * 64);
        }
#pragma unroll
        for (int j = 0; j < 2; j++) {
            int kr = bk + j * 32;
            uint32_t sw = swz(kr * 128 + bc * 16);
            cp16(sb + 16384 + sw, W1 + (size_t)(ch * 64 + kr) * HIDSZ + col0 + bc * 8);
            cp16(sb + 24576 + sw, W3 + (size_t)(ch * 64 + kr) * HIDSZ + col0 + bc * 8);
        }
    };

    float acc1[2][4][4] = {};
    float acc3[2][4][4] = {};

    const int nCh = DIMSZ / 64;   // 8
    loadStage(0, 0); CP_COMMIT();
    loadStage(1, 1); CP_COMMIT();

    int aRowF = (lane & 15);
    int aColF = (lane >> 4) << 3;
    int bKF = (lane & 7) + ((lane >> 3) & 1) * 8;
    int bNF = ((lane >> 4) & 1) * 8;

    for (int c = 0; c < nCh; c++) {
        if (c + 1 < nCh) { CP_WAIT(1); } else { CP_WAIT(0); }
        __syncthreads();
        if (c + 2 < nCh) {
            loadStage((c + 2) % 3, c + 2);
            CP_COMMIT();
        }

        uint32_t sA = base + (c % 3) * UP_STG;
        uint32_t sB1 = sA + 16384;
        uint32_t sB3 = sA + 24576;
#pragma unroll
        for (int kk = 0; kk < 4; kk++) {
            uint32_t a[2][4], b1[2][4], b3[2][4];
#pragma unroll
            for (int ma = 0; ma < 2; ma++) {
                int row = wr0 + ma * 16 + aRowF;
                uint32_t off = swz(row * 128 + (kk * 16 + aColF) * 2);
                LDSM4(a[ma], sA + off);
            }
#pragma unroll
            for (int nb = 0; nb < 2; nb++) {
                uint32_t off = swz((kk * 16 + bKF) * 128 + (wn0 + nb * 16 + bNF) * 2);
                LDSM4T(b1[nb], sB1 + off);
                LDSM4T(b3[nb], sB3 + off);
            }
#pragma unroll
            for (int ma = 0; ma < 2; ma++) {
#pragma unroll
                for (int nb = 0; nb < 2; nb++) {
#pragma unroll
                    for (int h = 0; h < 2; h++) {
                        MMA16816(acc1[ma][nb * 2 + h], a[ma], b1[nb][2 * h], b1[nb][2 * h + 1]);
                        MMA16816(acc3[ma][nb * 2 + h], a[ma], b3[nb][2 * h], b3[nb][2 * h + 1]);
                    }
                }
            }
        }
    }

    // epilogue: silu(acc1)*acc3 -> fp16 store
    int cRow = lane >> 2, cCol = (lane & 3) * 2;
#pragma unroll
    for (int ma = 0; ma < 2; ma++) {
#pragma unroll
        for (int half = 0; half < 2; half++) {
            int rl = wr0 + ma * 16 + half * 8 + cRow;
            int slot = sSlot[rl];
            if (slot < 0) continue;
            __half* hp = hout + (size_t)slot * HIDSZ + col0 + wn0;
#pragma unroll
            for (int na = 0; na < 4; na++) {
                float o0 = fast_silu_mul(acc1[ma][na][half * 2 + 0], acc3[ma][na][half * 2 + 0]);
                float o1 = fast_silu_mul(acc1[ma][na][half * 2 + 1], acc3[ma][na][half * 2 + 1]);
                *(__half2*)(hp + na * 8 + cCol) = __floats2half2_rn(o0, o1);
            }
        }
    }
}

// ================= down projection =================
// CTA 128(M) x 128(N), BK=64. 8 warps (2m x 4n), warp tile 64x32.
// Single __syncthreads per chunk. RED-add into out (pre-zeroed).
#define DN_STG 32768
__global__ __launch_bounds__(256, 2) void moe_down_h(const __half* __restrict__ w2h,
                                                     const __half* __restrict__ sw2h,
                                                     float* __restrict__ out) {
    extern __shared__ char dsm[];
    __shared__ int sSlot[128];

    int e = blockIdx.z;
    bool shared_e = (e == NE);
    int M = shared_e ? T_TOK : g_count[e];
    int row0 = blockIdx.x * 128;
    if (row0 >= M) return;
    int col0 = blockIdx.y * 128;
    const __half* W2 = shared_e ? sw2h : (w2h + (size_t)e * HIDSZ * DIMSZ);   // [H][D]
    const __half* hin = shared_e ? g_hs : g_h;

    uint32_t base = smem_u32(dsm);

    int tid = threadIdx.x, lane = tid & 31, warp = tid >> 5;
    if (tid < 128) {
        int r = row0 + tid;
        sSlot[tid] = (r < M) ? (shared_e ? r : g_list[e][r]) : -1;
    }
    __syncthreads();

    int wm = warp >> 2, wc = warp & 3;
    int wr0 = wm * 64, wn0 = wc * 32;
    int panel = wn0 >> 6;
    int wnp = wn0 & 63;

    int ar = tid >> 3, ac = tid & 7;

    // hoisted A-row base pointers (slot select done once, not per stage)
    const __half* aPtr[4];
#pragma unroll
    for (int j = 0; j < 4; j++) {
        int sl = sSlot[ar + j * 32];
        aPtr[j] = hin + (size_t)((sl < 0) ? 0 : sl) * HIDSZ + ac * 8;
    }

    auto loadStage = [&](int st, int ch) {
        uint32_t sb = base + st * DN_STG;
#pragma unroll
        for (int j = 0; j < 4; j++) {
            int row = ar + j * 32;
            uint32_t sw = swz(row * 128 + ac * 16);
            cp16(sb + sw, aPtr[j] + ch * 64);
        }
#pragma unroll
        for (int j = 0; j < 4; j++) {
            int idx = tid + j * 256;
            int pnl = idx >> 9;
            int rem = idx & 511;
            int kr = rem >> 3;
            int nc = rem & 7;
            uint32_t sw = swz(kr * 128 + nc * 16);
            cp16(sb + 16384 + pnl * 8192 + sw,
                 W2 + (size_t)(ch * 64 + kr) * DIMSZ + col0 + pnl * 64 + nc * 8);
        }
    };

    float acc[4][4][4] = {};

    const int nCh = HIDSZ / 64;   // 16
    loadStage(0, 0); CP_COMMIT();
    loadStage(1, 1); CP_COMMIT();

    int aRowF = (lane & 15);
    int aColF = (lane >> 4) << 3;
    int bKF = (lane & 7) + ((lane >> 3) & 1) * 8;
    int bNF = ((lane >> 4) & 1) * 8;

    for (int c = 0; c < nCh; c++) {
        if (c + 1 < nCh) { CP_WAIT(1); } else { CP_WAIT(0); }
        __syncthreads();
        if (c + 2 < nCh) {
            loadStage((c + 2) % 3, c + 2);
            CP_COMMIT();
        }

        uint32_t sA = base + (c % 3) * DN_STG;
        uint32_t sB = sA + 16384 + panel * 8192;
#pragma unroll
        for (int kk = 0; kk < 4; kk++) {
            uint32_t a[4][4], b[2][4];
#pragma unroll
            for (int ma = 0; ma < 4; ma++) {
                int row = wr0 + ma * 16 + aRowF;
                uint32_t off = swz(row * 128 + (kk * 16 + aColF) * 2);
                LDSM4(a[ma], sA + off);
            }
#pragma unroll
            for (int nb = 0; nb < 2; nb++) {
                uint32_t off = swz((kk * 16 + bKF) * 128 + (wnp + nb * 16 + bNF) * 2);
                LDSM4T(b[nb], sB + off);
            }
#pragma unroll
            for (int ma = 0; ma < 4; ma++) {
#pragma unroll
                for (int nb = 0; nb < 2; nb++) {
#pragma unroll
                    for (int h = 0; h < 2; h++) {
                        MMA16816(acc[ma][nb * 2 + h], a[ma], b[nb][2 * h], b[nb][2 * h + 1]);
                    }
                }
            }
        }
    }

    // epilogue: RED-add scaled results into out[token]
    int cRow = lane >> 2, cCol = (lane & 3) * 2;
#pragma unroll
    for (int ma = 0; ma < 4; ma++) {
#pragma unroll
        for (int half = 0; half < 2; half++) {
            int rl = wr0 + ma * 16 + half * 8 + cRow;
            int slot = sSlot[rl];
            if (slot < 0) continue;
            int token = shared_e ? slot : (slot >> 1);
            float scale = shared_e ? 1.f : g_p[slot];
            float* yp = out + (size_t)token * DIMSZ + col0 + wn0;
#pragma unroll
            for (int na = 0; na < 4; na++) {
                atomicAdd(yp + na * 8 + cCol + 0, scale * acc[ma][na][half * 2 + 0]);
                atomicAdd(yp + na * 8 + cCol + 1, scale * acc[ma][na][half * 2 + 1]);
            }
        }
    }
}

// ---------------- launcher ----------------
extern "C" void kernel_launch(void* const* d_in, const int* in_sizes, int n_in,
                              void* d_out, int out_size) {
    const float* x      = (const float*)d_in[0];
    const float* gate_w = (const float*)d_in[1];
    const float* biases = (const float*)d_in[2];
    const float* w1     = (const float*)d_in[3];
    const float* w3     = (const float*)d_in[4];
    const float* w2     = (const float*)d_in[5];
    const float* sw1    = (const float*)d_in[6];
    const float* sw3    = (const float*)d_in[7];
    const float* sw2    = (const float*)d_in[8];
    float* out          = (float*)d_out;

    const int upSmem = 3 * UP_STG;   // 98304
    const int dnSmem = 3 * DN_STG;   // 98304
    cudaFuncSetAttribute(moe_up_h,   cudaFuncAttributeMaxDynamicSharedMemorySize, upSmem);
    cudaFuncSetAttribute(moe_down_h, cudaFuncAttributeMaxDynamicSharedMemorySize, dnSmem);

    __half *w1h, *w3h, *w2h, *sw1h, *sw3h, *sw2h;
    cudaGetSymbolAddress((void**)&w1h,  g_w1h);
    cudaGetSymbolAddress((void**)&w3h,  g_w3h);
    cudaGetSymbolAddress((void**)&w2h,  g_w2h);
    cudaGetSymbolAddress((void**)&sw1h, g_sw1h);
    cudaGetSymbolAddress((void**)&sw3h, g_sw3h);
    cudaGetSymbolAddress((void**)&sw2h, g_sw2h);

    reset_counts_kernel<<<1, 32>>>();
    // router also converts x -> g_xh and zeroes out
    router_kernel<<<T_TOK / 8, 256>>>(x, gate_w, biases, out);
    cvt_all_kernel<<<(CVT_HALF + 255) / 256, 256>>>(w1, w3, w2, sw1, sw3, sw2);

    // fused: routed experts (z=0..7) + shared expert (z=8)
    moe_up_h<<<dim3(T_TOK / 128, HIDSZ / 64, NE + 1), 256, upSmem>>>(w1h, w3h, sw1h, sw3h);
    moe_down_h<<<dim3(T_TOK / 128, DIMSZ / 128, NE + 1), 256, dnSmem>>>(w2h, sw2h, out);
}